// round 15
// baseline (speedup 1.0000x reference)
#include <cuda_runtime.h>
#include <cuda_fp16.h>

#define NN 10000
#define NE 320000
#define FD 64
#define HD 256
#define GD 256
#define H3 768
#define MB 79                 // blocks per scale (ceil 10000/128)

#define ASTH 264              // h tile smem stride (halves)
#define XSTH 72               // x tile smem stride (halves)
#define ASM_H (128 * ASTH)    // halves per A tile (33792)
#define XSM_H (128 * XSTH)
#define CHUNK_WORDS 6144      // 192 rows x 64 halves = 24576 B
#define CHUNK_BYTES 24576
// smem: [ring 2x24576][Ah0][Ah1][Xh][mbar]
#define AH0_OFF (2 * CHUNK_BYTES)
#define AH1_OFF (AH0_OFF + ASM_H * 2)
#define XH_OFF (AH1_OFF + ASM_H * 2)
#define MB_OFF (XH_OFF + XSM_H * 2)
#define PERSIST_SMEM (MB_OFF + 32)

// ---------------- static scratch ----------------
__device__ unsigned d_WPK[3 * 20 * CHUNK_WORDS];  // repacked fp16 GRU weights
__device__ unsigned d_FWPK[256 / 64 * 768 / 64 * 2048];  // fusion W packed
__device__ unsigned d_G1PK[256 / 64 * 256 / 64 * 2048];
__device__ unsigned d_G2PK[256 / 64 * 256 / 64 * 2048];
__device__ float d_BIAS[3 * 768];
__device__ float d_COMB[NN * H3];
__device__ float d_TEMB[NN * GD];
__device__ float d_XL[NN * GD];
__device__ float d_G1[NN * GD];
__device__ float d_P[NN];
__device__ float d_Q[NN];
__device__ float d_SSUM[NN];
__device__ unsigned d_MENC[NN];
__device__ float d_SC[NE];
__device__ int d_CNT[NN];
__device__ int d_PTR[NN + 1];
__device__ int d_CUR[NN];
__device__ int d_EID[NE];

// ---------------- helpers ----------------
__device__ __forceinline__ float fsig(float x) {
    return __fdividef(1.f, 1.f + __expf(-x));
}
__device__ __forceinline__ float ftanh(float x) {
    x = fminf(fmaxf(x, -15.f), 15.f);
    float e = __expf(-2.f * x);
    return __fdividef(1.f - e, 1.f + e);
}

__device__ __forceinline__ unsigned smem_u32(const void* p) {
    return (unsigned)__cvta_generic_to_shared(p);
}

__device__ __forceinline__ void mma_f16(float* c, const unsigned* a, const unsigned* b) {
    asm volatile(
        "mma.sync.aligned.m16n8k16.row.col.f32.f16.f16.f32 "
        "{%0,%1,%2,%3},{%4,%5,%6,%7},{%8,%9},{%0,%1,%2,%3};"
        : "+f"(c[0]), "+f"(c[1]), "+f"(c[2]), "+f"(c[3])
        : "r"(a[0]), "r"(a[1]), "r"(a[2]), "r"(a[3]), "r"(b[0]), "r"(b[1]));
}

__device__ __forceinline__ void ldsm_x4(unsigned* r, unsigned addr) {
    asm volatile("ldmatrix.sync.aligned.m8n8.x4.shared.b16 {%0,%1,%2,%3}, [%4];"
                 : "=r"(r[0]), "=r"(r[1]), "=r"(r[2]), "=r"(r[3]) : "r"(addr));
}

#define MBAR_WAIT(addr, par) do {                                               \
    asm volatile(                                                               \
        "{\n\t.reg .pred P1;\n\t"                                               \
        "WAIT_%=:\n\t"                                                          \
        "mbarrier.try_wait.parity.acquire.cta.shared::cta.b64 P1, [%0], %1, 0x989680;\n\t" \
        "@P1 bra.uni DONE_%=;\n\t"                                              \
        "bra.uni WAIT_%=;\n\t"                                                  \
        "DONE_%=:\n\t}"                                                         \
        :: "r"(addr), "r"(par) : "memory");                                     \
} while (0)

// ---------------- bias fold ----------------
__global__ void k_prep_bias(const float* __restrict__ bih,
                            const float* __restrict__ bhh, int s) {
    int i = threadIdx.x;
    d_BIAS[s * 768 + i] = bih[i] + (i < 512 ? bhh[i] : 0.f);
}

// ---------------- GRU weight repack (fragment-ordered chunks) --------------
__global__ void k_pack(const float* __restrict__ whL, const float* __restrict__ wiL,
                       const float* __restrict__ whM, const float* __restrict__ wiM,
                       const float* __restrict__ whS, const float* __restrict__ wiS) {
    int W = blockIdx.x * 256 + threadIdx.x;
    if (W >= 3 * 20 * CHUNK_WORDS) return;
    int s = W / (20 * CHUNK_WORDS);
    int r = W % (20 * CHUNK_WORDS);
    int c = r / CHUNK_WORDS;
    int q = r % CHUNK_WORDS;
    int w = q & 1, lane = (q >> 1) & 31, ks = (q >> 6) & 3, u = (q >> 8) & 1;
    int gc = (q >> 9) % 3, wn = (q >> 9) / 3;
    int jc = c / 5, pc = c % 5;
    int grow = gc * 256 + jc * 64 + wn * 16 + u * 8 + (lane >> 2);
    int k0 = ks * 16 + 2 * (lane & 3) + w * 8;
    const float* wh = (s == 0) ? whL : ((s == 1) ? whM : whS);
    const float* wi = (s == 0) ? wiL : ((s == 1) ? wiM : wiS);
    const float* src = (pc < 4) ? (wh + (size_t)grow * 256 + pc * 64 + k0)
                                : (wi + (size_t)grow * 64 + k0);
    __half2 h2 = __floats2half2_rn(src[0], src[1]);
    d_WPK[W] = *(unsigned*)&h2;
}

// ---------------- generic GEMM weight repack ----------------
__global__ void k_packW(const float* __restrict__ W, unsigned* __restrict__ dst,
                        int N, int K) {
    int idx = blockIdx.x * 256 + threadIdx.x;
    int KC = K >> 6;
    int total = (N >> 6) * KC * 2048;
    if (idx >= total) return;
    int nb = idx / (KC * 2048);
    int r = idx % (KC * 2048);
    int kc = r / 2048;
    int q = r % 2048;
    int w = q & 1, lane = (q >> 1) & 31, ks = (q >> 6) & 3;
    int nt = (q >> 8) & 3, wn = (q >> 10) & 1;
    int n = nb * 64 + wn * 32 + nt * 8 + (lane >> 2);
    int k = kc * 64 + ks * 16 + 2 * (lane & 3) + w * 8;
    __half2 h2 = __floats2half2_rn(W[(size_t)n * K + k], W[(size_t)n * K + k + 1]);
    dst[idx] = *(unsigned*)&h2;
}

// ====== persistent GRU: 512 thr, 4m x 4n warp grid (2 m-tiles, 2 octets) ===
__global__ void __launch_bounds__(512) gru_persist(
    float* __restrict__ comb,
    const unsigned* __restrict__ wpk,
    const float* __restrict__ xL, const float* __restrict__ xM,
    const float* __restrict__ xS,
    const float* __restrict__ biasAll,
    const float* __restrict__ bhhL, const float* __restrict__ bhhM,
    const float* __restrict__ bhhS)
{
    extern __shared__ char smraw[];
    unsigned* Ring = (unsigned*)smraw;
    __half* Ah0 = (__half*)(smraw + AH0_OFF);
    __half* Ah1 = (__half*)(smraw + AH1_OFF);
    __half* Xh = (__half*)(smraw + XH_OFF);
    const unsigned ringaddr = smem_u32(smraw);
    const unsigned mbaddr = smem_u32(smraw + MB_OFF);
    const unsigned xh_base = smem_u32(Xh);

    const int tid = threadIdx.x;
    const int s = blockIdx.x / MB;
    const int m0 = (blockIdx.x % MB) * 128;
    const int T = (s == 0) ? 60 : ((s == 1) ? 30 : 8);
    const int co = (2 - s) * 256;   // column offset in COMB (hs|hm|hl)
    const float* xsrc = (s == 0) ? xL : ((s == 1) ? xM : xS);
    const float* bhh = (s == 0) ? bhhL : ((s == 1) ? bhhM : bhhS);
    const float* bias = biasAll + s * 768;

    const int lane = tid & 31, gid = lane >> 2, tig = lane & 3;
    const int warp = tid >> 5;
    const int wm = warp & 3, wn = warp >> 2;   // 4 m-groups x 4 n-groups
    const int lrow = tid >> 2;                 // 0..127 staging row
    const int cb16 = (tid & 3) * 16;           // 16-col stripe for staging
    const int i4 = lane >> 3, r8 = lane & 7;

    if (tid < 2) {
        asm volatile("mbarrier.init.shared.b64 [%0], %1;"
                     :: "r"(mbaddr + tid * 8), "r"(1u) : "memory");
    }
    // zero both A tiles (h0 = 0; rows >= NN stay zero forever)
    {
        unsigned* za = (unsigned*)Ah0;
        for (int i = tid; i < ASM_H; i += 512) za[i] = 0;
    }
    __syncthreads();

#define ISSUE_CHUNK(cc) do {                                                    \
        int sl_ = (cc) & 1;                                                     \
        unsigned mb_ = mbaddr + sl_ * 8;                                        \
        asm volatile("mbarrier.arrive.expect_tx.shared.b64 _, [%0], %1;"        \
                     :: "r"(mb_), "r"((unsigned)CHUNK_BYTES) : "memory");       \
        unsigned dst_ = ringaddr + sl_ * CHUNK_BYTES;                           \
        const void* src_ = (const char*)wpk +                                   \
                           ((size_t)(s * 20 + (cc))) * CHUNK_BYTES;             \
        asm volatile(                                                           \
            "cp.async.bulk.shared::cluster.global.mbarrier::complete_tx::bytes " \
            "[%0], [%1], %2, [%3];"                                             \
            :: "r"(dst_), "l"(src_), "r"((unsigned)CHUNK_BYTES), "r"(mb_)       \
            : "memory");                                                        \
    } while (0)

    for (int t = 0; t < T; t++) {
        const __half* Acur = (t & 1) ? Ah1 : Ah0;
        __half* Anxt = (t & 1) ? Ah0 : Ah1;
        const unsigned acur_base = smem_u32(Acur);

        if (tid == 0) { ISSUE_CHUNK(0); ISSUE_CHUNK(1); }

        // ---- stage x_t (128x64) into SMEM as fp16 (16 cols/thread) ----
        {
            int grow = m0 + lrow;
            bool ok = grow < NN;
            const float* xr = xsrc + ((size_t)grow * T + t) * 64;
            __half* dx = Xh + lrow * XSTH;
#pragma unroll
            for (int q = 0; q < 4; q++) {
                int col = cb16 + q * 4;
                float4 v = ok ? *(const float4*)(xr + col)
                              : make_float4(0.f, 0.f, 0.f, 0.f);
                *(__half2*)(dx + col)     = __floats2half2_rn(v.x, v.y);
                *(__half2*)(dx + col + 2) = __floats2half2_rn(v.z, v.w);
            }
        }
        __syncthreads();   // x staged; prev-step epilogue writes visible

#pragma unroll
        for (int jc = 0; jc < 4; jc++) {
            float acc[2][2][4][4];   // [m-tile][octet u][gate ci][reg]
#pragma unroll
            for (int i = 0; i < 2; i++)
#pragma unroll
                for (int u = 0; u < 2; u++)
#pragma unroll
                    for (int j = 0; j < 4; j++)
#pragma unroll
                        for (int r = 0; r < 4; r++) acc[i][u][j][r] = 0.f;

#pragma unroll
            for (int pc = 0; pc < 5; pc++) {
                const int c = jc * 5 + pc;
                const int slot = c & 1;
                MBAR_WAIT(mbaddr + slot * 8, (unsigned)((c >> 1) & 1));

                const unsigned* Bs = Ring + slot * CHUNK_WORDS;
                const unsigned abase = (pc < 4) ? acur_base : xh_base;
                const int astr = (pc < 4) ? ASTH : XSTH;
                const int kofs = (pc < 4) ? pc * 64 : 0;
                const unsigned arow0 =
                    abase + ((wm * 32 + (i4 & 1) * 8 + r8) * astr + kofs
                             + (i4 >> 1) * 8) * 2;
                const unsigned arow1 = arow0 + (unsigned)(16 * astr * 2);

#pragma unroll
                for (int ks = 0; ks < 4; ks++) {
                    unsigned af0[4], af1[4];
                    ldsm_x4(af0, arow0 + ks * 32);
                    ldsm_x4(af1, arow1 + ks * 32);
#pragma unroll
                    for (int gc = 0; gc < 3; gc++) {
                        const int ci = (pc == 4 && gc == 2) ? 3 : gc;
#pragma unroll
                        for (int u = 0; u < 2; u++) {
                            int fb = ((((wn * 3 + gc) * 2 + u) * 4 + ks) * 32
                                      + lane) * 2;
                            uint2 bf = *(const uint2*)(Bs + fb);
                            mma_f16(acc[0][u][ci], af0, &bf.x);
                            mma_f16(acc[1][u][ci], af1, &bf.x);
                        }
                    }
                }
                __syncthreads();           // slot consumed by all warps
                if (tid == 0 && c + 2 < 20) ISSUE_CHUNK(c + 2);
            }

            // ---- epilogue: GRU update; h read/write in SMEM fp16 ----
            const int j0 = jc * 64;
#pragma unroll
            for (int i = 0; i < 2; i++)
#pragma unroll
                for (int u = 0; u < 2; u++)
#pragma unroll
                    for (int h2 = 0; h2 < 2; h2++) {
                        int row = wm * 32 + i * 16 + gid + h2 * 8;
                        if (m0 + row >= NN) continue;
                        int jg = j0 + wn * 16 + u * 8 + 2 * tig;
                        float2 hp = __half22float2(
                            *(const __half2*)(Acur + row * ASTH + jg));
                        float2 ho;
                        {
                            float r0 = fsig(acc[i][u][0][h2 * 2 + 0] + bias[jg]);
                            float z0 = fsig(acc[i][u][1][h2 * 2 + 0] + bias[256 + jg]);
                            float n0 = ftanh(acc[i][u][3][h2 * 2 + 0] + bias[512 + jg] +
                                             r0 * (acc[i][u][2][h2 * 2 + 0] + bhh[512 + jg]));
                            ho.x = (1.f - z0) * n0 + z0 * hp.x;
                        }
                        {
                            float r1 = fsig(acc[i][u][0][h2 * 2 + 1] + bias[jg + 1]);
                            float z1 = fsig(acc[i][u][1][h2 * 2 + 1] + bias[256 + jg + 1]);
                            float n1 = ftanh(acc[i][u][3][h2 * 2 + 1] + bias[512 + jg + 1] +
                                             r1 * (acc[i][u][2][h2 * 2 + 1] + bhh[512 + jg + 1]));
                            ho.y = (1.f - z1) * n1 + z1 * hp.y;
                        }
                        *(__half2*)(Anxt + row * ASTH + jg) =
                            __floats2half2_rn(ho.x, ho.y);
                        if (t == T - 1)
                            *(float2*)(comb + (size_t)(m0 + row) * H3 + co + jg) = ho;
                    }
        }
        __syncthreads();   // epilogue STS visible; Xh free for next t
    }
#undef ISSUE_CHUNK
}

// ===== fp16 MMA GEMM (double-buffered A): C[M,256] = A[M,K]fp32 x Wpk^T ====
__global__ void __launch_bounds__(256) gemm_h(
    const float* __restrict__ A, int K,
    const unsigned* __restrict__ Bpk,
    const float* __restrict__ bias,
    float* __restrict__ C, int M, int relu)
{
    __shared__ __half Ash[2][128 * 72];
    const int tid = threadIdx.x, lane = tid & 31, warp = tid >> 5;
    const int wm = warp & 3, wn = warp >> 2;
    const int gid = lane >> 2, tig = lane & 3;
    const int i4 = lane >> 3, r8 = lane & 7;
    const int m0 = blockIdx.x * 128;
    const int KC = K >> 6;
    const unsigned* Bbase = Bpk + (size_t)blockIdx.y * KC * 2048;

    float acc[2][4][4];
#pragma unroll
    for (int i = 0; i < 2; i++)
#pragma unroll
        for (int nt = 0; nt < 4; nt++)
#pragma unroll
            for (int r = 0; r < 4; r++) acc[i][nt][r] = 0.f;

    const int srow = tid >> 1, scs = (tid & 1) * 32;
    const bool okrow = (m0 + srow) < M;

#define STAGE_A(kc, buf)                                                        \
    {                                                                           \
        const float* ar = A + (size_t)(m0 + srow) * K + (kc) * 64 + scs;        \
        __half* da = Ash[buf] + srow * 72 + scs;                                \
        _Pragma("unroll")                                                       \
        for (int qq = 0; qq < 8; qq++) {                                        \
            float4 v = okrow ? *(const float4*)(ar + qq * 4)                    \
                             : make_float4(0.f, 0.f, 0.f, 0.f);                 \
            *(__half2*)(da + qq * 4)     = __floats2half2_rn(v.x, v.y);         \
            *(__half2*)(da + qq * 4 + 2) = __floats2half2_rn(v.z, v.w);         \
        }                                                                       \
    }

    STAGE_A(0, 0);
    __syncthreads();

    for (int kc = 0; kc < KC; kc++) {
        if (kc + 1 < KC) STAGE_A(kc + 1, (kc + 1) & 1);
        const unsigned ab = smem_u32(Ash[kc & 1]);
        const unsigned* Bc = Bbase + kc * 2048;
#pragma unroll
        for (int ks = 0; ks < 4; ks++) {
            unsigned af[2][4];
#pragma unroll
            for (int i = 0; i < 2; i++) {
                int arow = wm * 32 + i * 16 + (i4 & 1) * 8 + r8;
                int acol = ks * 16 + (i4 >> 1) * 8;
                ldsm_x4(af[i], ab + (arow * 72 + acol) * 2);
            }
#pragma unroll
            for (int nt = 0; nt < 4; nt++) {
                int fb = (((wn * 4 + nt) * 4 + ks) * 32 + lane) * 2;
                uint2 bf = *(const uint2*)(Bc + fb);
#pragma unroll
                for (int i = 0; i < 2; i++)
                    mma_f16(acc[i][nt], af[i], &bf.x);
            }
        }
        __syncthreads();
    }
#undef STAGE_A

#pragma unroll
    for (int i = 0; i < 2; i++)
#pragma unroll
        for (int nt = 0; nt < 4; nt++)
#pragma unroll
            for (int h2 = 0; h2 < 2; h2++) {
                int row = m0 + wm * 32 + i * 16 + h2 * 8 + gid;
                if (row >= M) continue;
                int col = blockIdx.y * 64 + wn * 32 + nt * 8 + 2 * tig;
                float2 o;
                o.x = acc[i][nt][h2 * 2 + 0] + (bias ? bias[col] : 0.f);
                o.y = acc[i][nt][h2 * 2 + 1] + (bias ? bias[col + 1] : 0.f);
                if (relu) { o.x = fmaxf(o.x, 0.f); o.y = fmaxf(o.y, 0.f); }
                *(float2*)(C + (size_t)row * GD + col) = o;
            }
}

// ---------------- CSR build (by destination col) ----------------
__global__ void k_hist(const int* __restrict__ ei) {
    int e = blockIdx.x * 256 + threadIdx.x;
    if (e < NE) atomicAdd(&d_CNT[ei[NE + e]], 1);
}

__global__ void k_scan() {   // 1 block, 1024 threads
    __shared__ int part[1024];
    int t = threadIdx.x;
    int base = t * 10;
    int sum = 0;
#pragma unroll
    for (int i = 0; i < 10; i++) {
        int idx = base + i;
        if (idx < NN) sum += d_CNT[idx];
    }
    part[t] = sum;
    __syncthreads();
    for (int off = 1; off < 1024; off <<= 1) {
        int v = (t >= off) ? part[t - off] : 0;
        __syncthreads();
        part[t] += v;
        __syncthreads();
    }
    int run = (t > 0) ? part[t - 1] : 0;
#pragma unroll
    for (int i = 0; i < 10; i++) {
        int idx = base + i;
        if (idx < NN) {
            d_PTR[idx] = run;
            run += d_CNT[idx];
        }
    }
    if (t == 0) d_PTR[NN] = part[1023];
}

__global__ void k_scatter(const int* __restrict__ ei) {
    int e = blockIdx.x * 256 + threadIdx.x;
    if (e >= NE) return;
    int col = ei[NE + e];
    int pos = atomicAdd(&d_CUR[col], 1);
    d_EID[d_PTR[col] + pos] = e;
}

// ---------------- SAGE attention (decomposed scores) ----------------
__device__ __forceinline__ unsigned fenc(float f) {
    unsigned u = __float_as_uint(f);
    return (u & 0x80000000u) ? ~u : (u | 0x80000000u);
}
__device__ __forceinline__ float fdec(unsigned u) {
    u = (u & 0x80000000u) ? (u & 0x7fffffffu) : ~u;
    return __uint_as_float(u);
}

// p,q per node + init of MENC/SSUM (folded)
__global__ void k_pq(const float* __restrict__ aw) {
    int n = blockIdx.x * 8 + (threadIdx.x >> 5);
    int lane = threadIdx.x & 31;
    if (n >= NN) return;
    float p = 0.f, q = 0.f;
#pragma unroll
    for (int j = lane; j < 256; j += 32) {
        float v = d_XL[n * GD + j];
        p += v * aw[j];
        q += v * aw[256 + j];
    }
#pragma unroll
    for (int o = 16; o; o >>= 1) {
        p += __shfl_xor_sync(0xffffffffu, p, o);
        q += __shfl_xor_sync(0xffffffffu, q, o);
    }
    if (lane == 0) {
        d_P[n] = p; d_Q[n] = q;
        d_MENC[n] = 0x007fffffu;   // fenc(-inf)
        d_SSUM[n] = 0.f;
    }
}

__global__ void k_edge1(const int* __restrict__ ei, const float* __restrict__ ea,
                        const float* __restrict__ aw, const float* __restrict__ ab) {
    int e = blockIdx.x * 256 + threadIdx.x;
    if (e >= NE) return;
    int row = ei[e], col = ei[NE + e];
    float sc = d_P[row] + d_Q[col] + aw[512] * ea[e] + ab[0];
    d_SC[e] = sc;
    atomicMax(&d_MENC[row], fenc(sc));
}

__global__ void k_edge2(const int* __restrict__ ei) {
    int e = blockIdx.x * 256 + threadIdx.x;
    if (e >= NE) return;
    int row = ei[e];
    float m = fdec(d_MENC[row]);
    float ex = __expf(d_SC[e] - m);
    d_SC[e] = ex;
    atomicAdd(&d_SSUM[row], ex);
}

// CSR aggregation layer 1: alpha division folded in; relu; -> G1
__global__ void __launch_bounds__(256) k_agg(const int* __restrict__ ei,
                                             float* __restrict__ dst) {
    int node = blockIdx.x * 4 + (threadIdx.x >> 6);
    int l = threadIdx.x & 63;
    int beg = d_PTR[node], end = d_PTR[node + 1];
    float4 acc = make_float4(0.f, 0.f, 0.f, 0.f);
    for (int idx = beg; idx < end; idx++) {
        int e = d_EID[idx];
        int row = ei[e];
        float alpha = __fdividef(d_SC[e], d_SSUM[row] + 1e-16f);
        float4 v = *(const float4*)&d_XL[(size_t)row * GD + l * 4];
        acc.x += alpha * v.x; acc.y += alpha * v.y;
        acc.z += alpha * v.z; acc.w += alpha * v.w;
    }
    float4 o;
    o.x = fmaxf(acc.x, 0.f); o.y = fmaxf(acc.y, 0.f);
    o.z = fmaxf(acc.z, 0.f); o.w = fmaxf(acc.w, 0.f);
    *(float4*)&dst[(size_t)node * GD + l * 4] = o;
}

// CSR aggregation layer 2 + residual + heads (fused; G2 never stored)
__global__ void __launch_bounds__(256) k_agg2(const int* __restrict__ ei,
                                              const float* __restrict__ addsrc,
                                              const float* __restrict__ impW,
                                              const float* __restrict__ impb,
                                              const float* __restrict__ uncW,
                                              const float* __restrict__ uncb,
                                              float* __restrict__ out) {
    __shared__ float red[4][2][2];
    int nib = threadIdx.x >> 6;
    int node = blockIdx.x * 4 + nib;   // NN % 4 == 0: always valid
    int l = threadIdx.x & 63;
    int beg = d_PTR[node], end = d_PTR[node + 1];
    float4 acc = make_float4(0.f, 0.f, 0.f, 0.f);
    for (int idx = beg; idx < end; idx++) {
        int e = d_EID[idx];
        int row = ei[e];
        float alpha = __fdividef(d_SC[e], d_SSUM[row] + 1e-16f);
        float4 v = *(const float4*)&d_XL[(size_t)row * GD + l * 4];
        acc.x += alpha * v.x; acc.y += alpha * v.y;
        acc.z += alpha * v.z; acc.w += alpha * v.w;
    }
    float4 a4 = *(const float4*)&addsrc[(size_t)node * GD + l * 4];
    float4 o;
    o.x = fmaxf(acc.x, 0.f) + a4.x; o.y = fmaxf(acc.y, 0.f) + a4.y;
    o.z = fmaxf(acc.z, 0.f) + a4.z; o.w = fmaxf(acc.w, 0.f) + a4.w;
    float4 iw = *(const float4*)&impW[l * 4];
    float4 uw = *(const float4*)&uncW[l * 4];
    float pa = o.x * iw.x + o.y * iw.y + o.z * iw.z + o.w * iw.w;
    float pb = o.x * uw.x + o.y * uw.y + o.z * uw.z + o.w * uw.w;
#pragma unroll
    for (int off = 16; off; off >>= 1) {
        pa += __shfl_xor_sync(0xffffffffu, pa, off);
        pb += __shfl_xor_sync(0xffffffffu, pb, off);
    }
    int half = (threadIdx.x >> 5) & 1;
    if ((threadIdx.x & 31) == 0) {
        red[nib][half][0] = pa;
        red[nib][half][1] = pb;
    }
    __syncthreads();
    if (l == 0) {
        float a = red[nib][0][0] + red[nib][1][0] + impb[0];
        float b = red[nib][0][1] + red[nib][1][1] + uncb[0];
        out[node] = tanhf(a);
        out[NN + node] = 1.f / (1.f + expf(-b));
    }
}

// ---------------- host orchestration ----------------
extern "C" void kernel_launch(void* const* d_in, const int* in_sizes, int n_in,
                              void* d_out, int out_size)
{
    const float* x_s = (const float*)d_in[0];
    const float* x_m = (const float*)d_in[1];
    const float* x_l = (const float*)d_in[2];
    const int*   ei  = (const int*)d_in[3];
    const float* ea  = (const float*)d_in[4];
    // scale order here: 0=long, 1=medium, 2=short
    const float* Wih[3] = {(const float*)d_in[13], (const float*)d_in[9], (const float*)d_in[5]};
    const float* Whh[3] = {(const float*)d_in[14], (const float*)d_in[10], (const float*)d_in[6]};
    const float* bih[3] = {(const float*)d_in[15], (const float*)d_in[11], (const float*)d_in[7]};
    const float* bhh[3] = {(const float*)d_in[16], (const float*)d_in[12], (const float*)d_in[8]};
    const float* fW   = (const float*)d_in[17];
    const float* fb   = (const float*)d_in[18];
    const float* g1W  = (const float*)d_in[19];
    const float* g1aw = (const float*)d_in[20];
    const float* g1ab = (const float*)d_in[21];
    const float* g2W  = (const float*)d_in[22];
    const float* g2aw = (const float*)d_in[23];
    const float* g2ab = (const float*)d_in[24];
    const float* impW = (const float*)d_in[25];
    const float* impb = (const float*)d_in[26];
    const float* uncW = (const float*)d_in[27];
    const float* uncb = (const float*)d_in[28];

    void *pWPK, *pFW, *pG1W, *pG2W, *pBIAS;
    void *pCOMB, *pTEMB, *pXL, *pG1, *pCNT, *pCUR;
    cudaGetSymbolAddress(&pWPK, d_WPK);
    cudaGetSymbolAddress(&pFW, d_FWPK);
    cudaGetSymbolAddress(&pG1W, d_G1PK);
    cudaGetSymbolAddress(&pG2W, d_G2PK);
    cudaGetSymbolAddress(&pBIAS, d_BIAS);
    cudaGetSymbolAddress(&pCOMB, d_COMB);
    cudaGetSymbolAddress(&pTEMB, d_TEMB);
    cudaGetSymbolAddress(&pXL, d_XL);
    cudaGetSymbolAddress(&pG1, d_G1);
    cudaGetSymbolAddress(&pCNT, d_CNT);
    cudaGetSymbolAddress(&pCUR, d_CUR);
    unsigned* WPKp = (unsigned*)pWPK;
    float* BIASp = (float*)pBIAS;
    float* COMB = (float*)pCOMB; float* TEMB = (float*)pTEMB;
    float* XL = (float*)pXL;
    float* G1 = (float*)pG1;

    cudaFuncSetAttribute(gru_persist,
                         cudaFuncAttributeMaxDynamicSharedMemorySize, PERSIST_SMEM);

    // ---- fold biases + repack weights ----
    for (int s = 0; s < 3; s++)
        k_prep_bias<<<1, 768>>>(bih[s], bhh[s], s);
    k_pack<<<(3 * 20 * CHUNK_WORDS + 255) / 256, 256>>>(
        Whh[0], Wih[0], Whh[1], Wih[1], Whh[2], Wih[2]);
    k_packW<<<(4 * 12 * 2048 + 255) / 256, 256>>>(fW, (unsigned*)pFW, 256, 768);
    k_packW<<<(4 * 4 * 2048 + 255) / 256, 256>>>(g1W, (unsigned*)pG1W, 256, 256);
    k_packW<<<(4 * 4 * 2048 + 255) / 256, 256>>>(g2W, (unsigned*)pG2W, 256, 256);

    // ---- CSR build (edge_index reused by both SAGE layers) ----
    cudaMemsetAsync(pCNT, 0, NN * sizeof(int));
    cudaMemsetAsync(pCUR, 0, NN * sizeof(int));
    k_hist<<<(NE + 255) / 256, 256>>>(ei);
    k_scan<<<1, 1024>>>();
    k_scatter<<<(NE + 255) / 256, 256>>>(ei);

    // ---- persistent recurrence (finals written directly into COMB) ----
    gru_persist<<<3 * MB, 512, PERSIST_SMEM>>>(
        COMB, WPKp, x_l, x_m, x_s, BIASp, bhh[0], bhh[1], bhh[2]);

    // ---- fusion ----
    dim3 gH((NN + 127) / 128, 4);
    gemm_h<<<gH, 256>>>(COMB, 768, (unsigned*)pFW, fb, TEMB, NN, 1);

    // ---- SAGE layer 1 ----
    gemm_h<<<gH, 256>>>(TEMB, 256, (unsigned*)pG1W, nullptr, XL, NN, 0);
    k_pq<<<(NN + 7) / 8, 256>>>(g1aw);
    k_edge1<<<(NE + 255) / 256, 256>>>(ei, ea, g1aw, g1ab);
    k_edge2<<<(NE + 255) / 256, 256>>>(ei);
    k_agg<<<NN / 4, 256>>>(ei, G1);

    // ---- SAGE layer 2 (aggregation + residual + heads fused) ----
    gemm_h<<<gH, 256>>>(G1, 256, (unsigned*)pG2W, nullptr, XL, NN, 0);
    k_pq<<<(NN + 7) / 8, 256>>>(g2aw);
    k_edge1<<<(NE + 255) / 256, 256>>>(ei, ea, g2aw, g2ab);
    k_edge2<<<(NE + 255) / 256, 256>>>(ei);
    k_agg2<<<NN / 4, 256>>>(ei, TEMB, impW, impb, uncW, uncb, (float*)d_out);
}

// round 16
// speedup vs baseline: 1.1015x; 1.1015x over previous
#include <cuda_runtime.h>
#include <cuda_fp16.h>

#define NN 10000
#define NE 320000
#define FD 64
#define HD 256
#define GD 256
#define H3 768
#define MB 79                 // blocks per scale (ceil 10000/128)

#define ASTH 264              // h tile smem stride (halves)
#define XSTH 72               // x tile smem stride (halves)
#define ASM_H (128 * ASTH)    // halves per A tile (33792)
#define XSM_H (128 * XSTH)
#define CHUNK_WORDS 6144      // 192 rows x 64 halves = 24576 B
#define CHUNK_BYTES 24576
// smem: [ring 3x24576][Ah0][Ah1][Xh][mbar]
#define AH0_OFF (3 * CHUNK_BYTES)
#define AH1_OFF (AH0_OFF + ASM_H * 2)
#define XH_OFF (AH1_OFF + ASM_H * 2)
#define MB_OFF (XH_OFF + XSM_H * 2)
#define PERSIST_SMEM (MB_OFF + 32)

// ---------------- static scratch ----------------
__device__ unsigned d_WPK[3 * 20 * CHUNK_WORDS];  // repacked fp16 GRU weights
__device__ unsigned d_FWPK[256 / 64 * 768 / 64 * 2048];  // fusion W packed
__device__ unsigned d_G1PK[256 / 64 * 256 / 64 * 2048];
__device__ unsigned d_G2PK[256 / 64 * 256 / 64 * 2048];
__device__ float d_BIAS[3 * 768];
__device__ float d_COMB[NN * H3];
__device__ float d_TEMB[NN * GD];
__device__ float d_XL[NN * GD];
__device__ float d_G1[NN * GD];
__device__ float d_P[NN];
__device__ float d_Q[NN];
__device__ float d_SSUM[NN];
__device__ unsigned d_MENC[NN];
__device__ float d_SC[NE];
__device__ int d_CNT[NN];
__device__ int d_PTR[NN + 1];
__device__ int d_CUR[NN];
__device__ int d_EID[NE];

// ---------------- helpers ----------------
__device__ __forceinline__ float fsig(float x) {
    return __fdividef(1.f, 1.f + __expf(-x));
}
__device__ __forceinline__ float ftanh(float x) {
    x = fminf(fmaxf(x, -15.f), 15.f);
    float e = __expf(-2.f * x);
    return __fdividef(1.f - e, 1.f + e);
}

__device__ __forceinline__ unsigned smem_u32(const void* p) {
    return (unsigned)__cvta_generic_to_shared(p);
}

__device__ __forceinline__ void mma_f16(float* c, const unsigned* a, const unsigned* b) {
    asm volatile(
        "mma.sync.aligned.m16n8k16.row.col.f32.f16.f16.f32 "
        "{%0,%1,%2,%3},{%4,%5,%6,%7},{%8,%9},{%0,%1,%2,%3};"
        : "+f"(c[0]), "+f"(c[1]), "+f"(c[2]), "+f"(c[3])
        : "r"(a[0]), "r"(a[1]), "r"(a[2]), "r"(a[3]), "r"(b[0]), "r"(b[1]));
}

__device__ __forceinline__ void ldsm_x4(unsigned* r, unsigned addr) {
    asm volatile("ldmatrix.sync.aligned.m8n8.x4.shared.b16 {%0,%1,%2,%3}, [%4];"
                 : "=r"(r[0]), "=r"(r[1]), "=r"(r[2]), "=r"(r[3]) : "r"(addr));
}

#define MBAR_WAIT(addr, par) do {                                               \
    asm volatile(                                                               \
        "{\n\t.reg .pred P1;\n\t"                                               \
        "WAIT_%=:\n\t"                                                          \
        "mbarrier.try_wait.parity.acquire.cta.shared::cta.b64 P1, [%0], %1, 0x989680;\n\t" \
        "@P1 bra.uni DONE_%=;\n\t"                                              \
        "bra.uni WAIT_%=;\n\t"                                                  \
        "DONE_%=:\n\t}"                                                         \
        :: "r"(addr), "r"(par) : "memory");                                     \
} while (0)

// ---------------- bias fold ----------------
__global__ void k_prep_bias(const float* __restrict__ bih,
                            const float* __restrict__ bhh, int s) {
    int i = threadIdx.x;
    d_BIAS[s * 768 + i] = bih[i] + (i < 512 ? bhh[i] : 0.f);
}

// ---------------- GRU weight repack (fragment-ordered chunks) --------------
__global__ void k_pack(const float* __restrict__ whL, const float* __restrict__ wiL,
                       const float* __restrict__ whM, const float* __restrict__ wiM,
                       const float* __restrict__ whS, const float* __restrict__ wiS) {
    int W = blockIdx.x * 256 + threadIdx.x;
    if (W >= 3 * 20 * CHUNK_WORDS) return;
    int s = W / (20 * CHUNK_WORDS);
    int r = W % (20 * CHUNK_WORDS);
    int c = r / CHUNK_WORDS;
    int q = r % CHUNK_WORDS;
    int w = q & 1, lane = (q >> 1) & 31, ks = (q >> 6) & 3, u = (q >> 8) & 1;
    int gc = (q >> 9) % 3, wn = (q >> 9) / 3;
    int jc = c / 5, pc = c % 5;
    int grow = gc * 256 + jc * 64 + wn * 16 + u * 8 + (lane >> 2);
    int k0 = ks * 16 + 2 * (lane & 3) + w * 8;
    const float* wh = (s == 0) ? whL : ((s == 1) ? whM : whS);
    const float* wi = (s == 0) ? wiL : ((s == 1) ? wiM : wiS);
    const float* src = (pc < 4) ? (wh + (size_t)grow * 256 + pc * 64 + k0)
                                : (wi + (size_t)grow * 64 + k0);
    __half2 h2 = __floats2half2_rn(src[0], src[1]);
    d_WPK[W] = *(unsigned*)&h2;
}

// ---------------- generic GEMM weight repack ----------------
__global__ void k_packW(const float* __restrict__ W, unsigned* __restrict__ dst,
                        int N, int K) {
    int idx = blockIdx.x * 256 + threadIdx.x;
    int KC = K >> 6;
    int total = (N >> 6) * KC * 2048;
    if (idx >= total) return;
    int nb = idx / (KC * 2048);
    int r = idx % (KC * 2048);
    int kc = r / 2048;
    int q = r % 2048;
    int w = q & 1, lane = (q >> 1) & 31, ks = (q >> 6) & 3;
    int nt = (q >> 8) & 3, wn = (q >> 10) & 1;
    int n = nb * 64 + wn * 32 + nt * 8 + (lane >> 2);
    int k = kc * 64 + ks * 16 + 2 * (lane & 3) + w * 8;
    __half2 h2 = __floats2half2_rn(W[(size_t)n * K + k], W[(size_t)n * K + k + 1]);
    dst[idx] = *(unsigned*)&h2;
}

// == persistent GRU: 1024 thr, 4m x 8n; 3-slot ring, sync every 2 chunks ====
__global__ void __launch_bounds__(1024) gru_persist(
    float* __restrict__ comb,
    const unsigned* __restrict__ wpk,
    const float* __restrict__ xL, const float* __restrict__ xM,
    const float* __restrict__ xS,
    const float* __restrict__ biasAll,
    const float* __restrict__ bhhL, const float* __restrict__ bhhM,
    const float* __restrict__ bhhS)
{
    extern __shared__ char smraw[];
    unsigned* Ring = (unsigned*)smraw;
    __half* Ah0 = (__half*)(smraw + AH0_OFF);
    __half* Ah1 = (__half*)(smraw + AH1_OFF);
    __half* Xh = (__half*)(smraw + XH_OFF);
    const unsigned ringaddr = smem_u32(smraw);
    const unsigned mbaddr = smem_u32(smraw + MB_OFF);
    const unsigned xh_base = smem_u32(Xh);

    const int tid = threadIdx.x;
    const int s = blockIdx.x / MB;
    const int m0 = (blockIdx.x % MB) * 128;
    const int T = (s == 0) ? 60 : ((s == 1) ? 30 : 8);
    const int co = (2 - s) * 256;   // column offset in COMB (hs|hm|hl)
    const float* xsrc = (s == 0) ? xL : ((s == 1) ? xM : xS);
    const float* bhh = (s == 0) ? bhhL : ((s == 1) ? bhhM : bhhS);
    const float* bias = biasAll + s * 768;

    const int lane = tid & 31, gid = lane >> 2, tig = lane & 3;
    const int warp = tid >> 5;
    const int wm = warp & 3, wn = warp >> 2;   // 4 m-groups x 8 n-octets
    const int lrow = tid >> 3;
    const int cbase = (tid & 7) * 4;
    const int i4 = lane >> 3, r8 = lane & 7;
    // B fragment base index component for this wn (old (wn>>1, u=wn&1) layout)
    const int bq = ((wn >> 1) * 3) * 2 + (wn & 1);   // gc term added as gc*2

    if (tid < 3) {
        asm volatile("mbarrier.init.shared.b64 [%0], %1;"
                     :: "r"(mbaddr + tid * 8), "r"(1u) : "memory");
    }
    // zero both A tiles (h0 = 0; rows >= NN stay zero forever)
    {
        unsigned* za = (unsigned*)Ah0;
        for (int i = tid; i < ASM_H; i += 1024) za[i] = 0;
    }
    __syncthreads();

#define ISSUE_CHUNK(cc) do {                                                    \
        int sl_ = (cc) % 3;                                                     \
        unsigned mb_ = mbaddr + sl_ * 8;                                        \
        asm volatile("mbarrier.arrive.expect_tx.shared.b64 _, [%0], %1;"        \
                     :: "r"(mb_), "r"((unsigned)CHUNK_BYTES) : "memory");       \
        unsigned dst_ = ringaddr + sl_ * CHUNK_BYTES;                           \
        const void* src_ = (const char*)wpk +                                   \
                           ((size_t)(s * 20 + (cc))) * CHUNK_BYTES;             \
        asm volatile(                                                           \
            "cp.async.bulk.shared::cluster.global.mbarrier::complete_tx::bytes " \
            "[%0], [%1], %2, [%3];"                                             \
            :: "r"(dst_), "l"(src_), "r"((unsigned)CHUNK_BYTES), "r"(mb_)       \
            : "memory");                                                        \
    } while (0)

    for (int t = 0; t < T; t++) {
        const __half* Acur = (t & 1) ? Ah1 : Ah0;
        __half* Anxt = (t & 1) ? Ah0 : Ah1;
        const unsigned acur_base = smem_u32(Acur);

        if (tid == 0) { ISSUE_CHUNK(0); ISSUE_CHUNK(1); ISSUE_CHUNK(2); }

        // ---- stage x_t (128x64) into SMEM as fp16 ----
        {
            int grow = m0 + lrow;
            bool ok = grow < NN;
            const float* xr = xsrc + ((size_t)grow * T + t) * 64;
            __half* dx = Xh + lrow * XSTH;
#pragma unroll
            for (int q = 0; q < 2; q++) {
                int col = cbase + q * 32;
                float4 v = ok ? *(const float4*)(xr + col)
                              : make_float4(0.f, 0.f, 0.f, 0.f);
                *(__half2*)(dx + col)     = __floats2half2_rn(v.x, v.y);
                *(__half2*)(dx + col + 2) = __floats2half2_rn(v.z, v.w);
            }
        }
        __syncthreads();   // x staged; prev-step epilogue writes visible

#pragma unroll
        for (int jc = 0; jc < 4; jc++) {
            float acc[2][4][4];   // [m-tile][gate ci][reg]
#pragma unroll
            for (int i = 0; i < 2; i++)
#pragma unroll
                for (int j = 0; j < 4; j++)
#pragma unroll
                    for (int r = 0; r < 4; r++) acc[i][j][r] = 0.f;

#pragma unroll
            for (int pc = 0; pc < 5; pc++) {
                const int c = jc * 5 + pc;
                const int slot = c % 3;
                const int nuse = (slot == 2) ? 6 : 7;
                unsigned par = (unsigned)((t * nuse + c / 3) & 1);
                MBAR_WAIT(mbaddr + slot * 8, par);

                const unsigned* Bs = Ring + slot * CHUNK_WORDS;
                const unsigned abase = (pc < 4) ? acur_base : xh_base;
                const int astr = (pc < 4) ? ASTH : XSTH;
                const int kofs = (pc < 4) ? pc * 64 : 0;
                const unsigned arow0 =
                    abase + ((wm * 32 + (i4 & 1) * 8 + r8) * astr + kofs
                             + (i4 >> 1) * 8) * 2;
                const unsigned arow1 = arow0 + (unsigned)(16 * astr * 2);

#pragma unroll
                for (int ks = 0; ks < 4; ks++) {
                    unsigned af0[4], af1[4];
                    ldsm_x4(af0, arow0 + ks * 32);
                    ldsm_x4(af1, arow1 + ks * 32);
#pragma unroll
                    for (int gc = 0; gc < 3; gc++) {
                        const int ci = (pc == 4 && gc == 2) ? 3 : gc;
                        int fb = (((bq + gc * 2) * 4 + ks) * 32 + lane) * 2;
                        uint2 bf = *(const uint2*)(Bs + fb);
                        mma_f16(acc[0][ci], af0, &bf.x);
                        mma_f16(acc[1][ci], af1, &bf.x);
                    }
                }
                // sync every 2nd chunk; recycle 2 slots per sync
                if (c & 1) {
                    __syncthreads();
                    if (tid == 0) {
                        if (c + 2 < 20) ISSUE_CHUNK(c + 2);
                        if (c + 3 < 20) ISSUE_CHUNK(c + 3);
                    }
                }
            }

            // ---- epilogue: GRU update; h read/write in SMEM fp16 ----
            // (no sync needed: acc is private; Anxt writes are per-thread-owned
            //  and not read until after next step's stage-x __syncthreads)
            const int j0 = jc * 64;
#pragma unroll
            for (int i = 0; i < 2; i++)
#pragma unroll
                for (int h2 = 0; h2 < 2; h2++) {
                    int row = wm * 32 + i * 16 + gid + h2 * 8;
                    if (m0 + row >= NN) continue;
                    int jg = j0 + wn * 8 + 2 * tig;
                    float2 hp = __half22float2(
                        *(const __half2*)(Acur + row * ASTH + jg));
                    float2 ho;
                    {
                        float r0 = fsig(acc[i][0][h2 * 2 + 0] + bias[jg]);
                        float z0 = fsig(acc[i][1][h2 * 2 + 0] + bias[256 + jg]);
                        float n0 = ftanh(acc[i][3][h2 * 2 + 0] + bias[512 + jg] +
                                         r0 * (acc[i][2][h2 * 2 + 0] + bhh[512 + jg]));
                        ho.x = (1.f - z0) * n0 + z0 * hp.x;
                    }
                    {
                        float r1 = fsig(acc[i][0][h2 * 2 + 1] + bias[jg + 1]);
                        float z1 = fsig(acc[i][1][h2 * 2 + 1] + bias[256 + jg + 1]);
                        float n1 = ftanh(acc[i][3][h2 * 2 + 1] + bias[512 + jg + 1] +
                                         r1 * (acc[i][2][h2 * 2 + 1] + bhh[512 + jg + 1]));
                        ho.y = (1.f - z1) * n1 + z1 * hp.y;
                    }
                    *(__half2*)(Anxt + row * ASTH + jg) =
                        __floats2half2_rn(ho.x, ho.y);
                    if (t == T - 1)
                        *(float2*)(comb + (size_t)(m0 + row) * H3 + co + jg) = ho;
                }
        }
        // step ends right after sync at c==19 + epilogue; next iteration's
        // stage-x sync orders epilogue writes before their first use.
    }
#undef ISSUE_CHUNK
}

// ===== fp16 MMA GEMM (double-buffered A): C[M,256] = A[M,K]fp32 x Wpk^T ====
__global__ void __launch_bounds__(256) gemm_h(
    const float* __restrict__ A, int K,
    const unsigned* __restrict__ Bpk,
    const float* __restrict__ bias,
    float* __restrict__ C, int M, int relu)
{
    __shared__ __half Ash[2][128 * 72];
    const int tid = threadIdx.x, lane = tid & 31, warp = tid >> 5;
    const int wm = warp & 3, wn = warp >> 2;
    const int gid = lane >> 2, tig = lane & 3;
    const int i4 = lane >> 3, r8 = lane & 7;
    const int m0 = blockIdx.x * 128;
    const int KC = K >> 6;
    const unsigned* Bbase = Bpk + (size_t)blockIdx.y * KC * 2048;

    float acc[2][4][4];
#pragma unroll
    for (int i = 0; i < 2; i++)
#pragma unroll
        for (int nt = 0; nt < 4; nt++)
#pragma unroll
            for (int r = 0; r < 4; r++) acc[i][nt][r] = 0.f;

    const int srow = tid >> 1, scs = (tid & 1) * 32;
    const bool okrow = (m0 + srow) < M;

#define STAGE_A(kc, buf)                                                        \
    {                                                                           \
        const float* ar = A + (size_t)(m0 + srow) * K + (kc) * 64 + scs;        \
        __half* da = Ash[buf] + srow * 72 + scs;                                \
        _Pragma("unroll")                                                       \
        for (int qq = 0; qq < 8; qq++) {                                        \
            float4 v = okrow ? *(const float4*)(ar + qq * 4)                    \
                             : make_float4(0.f, 0.f, 0.f, 0.f);                 \
            *(__half2*)(da + qq * 4)     = __floats2half2_rn(v.x, v.y);         \
            *(__half2*)(da + qq * 4 + 2) = __floats2half2_rn(v.z, v.w);         \
        }                                                                       \
    }

    STAGE_A(0, 0);
    __syncthreads();

    for (int kc = 0; kc < KC; kc++) {
        if (kc + 1 < KC) STAGE_A(kc + 1, (kc + 1) & 1);
        const unsigned ab = smem_u32(Ash[kc & 1]);
        const unsigned* Bc = Bbase + kc * 2048;
#pragma unroll
        for (int ks = 0; ks < 4; ks++) {
            unsigned af[2][4];
#pragma unroll
            for (int i = 0; i < 2; i++) {
                int arow = wm * 32 + i * 16 + (i4 & 1) * 8 + r8;
                int acol = ks * 16 + (i4 >> 1) * 8;
                ldsm_x4(af[i], ab + (arow * 72 + acol) * 2);
            }
#pragma unroll
            for (int nt = 0; nt < 4; nt++) {
                int fb = (((wn * 4 + nt) * 4 + ks) * 32 + lane) * 2;
                uint2 bf = *(const uint2*)(Bc + fb);
#pragma unroll
                for (int i = 0; i < 2; i++)
                    mma_f16(acc[i][nt], af[i], &bf.x);
            }
        }
        __syncthreads();
    }
#undef STAGE_A

#pragma unroll
    for (int i = 0; i < 2; i++)
#pragma unroll
        for (int nt = 0; nt < 4; nt++)
#pragma unroll
            for (int h2 = 0; h2 < 2; h2++) {
                int row = m0 + wm * 32 + i * 16 + h2 * 8 + gid;
                if (row >= M) continue;
                int col = blockIdx.y * 64 + wn * 32 + nt * 8 + 2 * tig;
                float2 o;
                o.x = acc[i][nt][h2 * 2 + 0] + (bias ? bias[col] : 0.f);
                o.y = acc[i][nt][h2 * 2 + 1] + (bias ? bias[col + 1] : 0.f);
                if (relu) { o.x = fmaxf(o.x, 0.f); o.y = fmaxf(o.y, 0.f); }
                *(float2*)(C + (size_t)row * GD + col) = o;
            }
}

// ---------------- CSR build (by destination col) ----------------
__global__ void k_hist(const int* __restrict__ ei) {
    int e = blockIdx.x * 256 + threadIdx.x;
    if (e < NE) atomicAdd(&d_CNT[ei[NE + e]], 1);
}

__global__ void k_scan() {   // 1 block, 1024 threads
    __shared__ int part[1024];
    int t = threadIdx.x;
    int base = t * 10;
    int sum = 0;
#pragma unroll
    for (int i = 0; i < 10; i++) {
        int idx = base + i;
        if (idx < NN) sum += d_CNT[idx];
    }
    part[t] = sum;
    __syncthreads();
    for (int off = 1; off < 1024; off <<= 1) {
        int v = (t >= off) ? part[t - off] : 0;
        __syncthreads();
        part[t] += v;
        __syncthreads();
    }
    int run = (t > 0) ? part[t - 1] : 0;
#pragma unroll
    for (int i = 0; i < 10; i++) {
        int idx = base + i;
        if (idx < NN) {
            d_PTR[idx] = run;
            run += d_CNT[idx];
        }
    }
    if (t == 0) d_PTR[NN] = part[1023];
}

__global__ void k_scatter(const int* __restrict__ ei) {
    int e = blockIdx.x * 256 + threadIdx.x;
    if (e >= NE) return;
    int col = ei[NE + e];
    int pos = atomicAdd(&d_CUR[col], 1);
    d_EID[d_PTR[col] + pos] = e;
}

// ---------------- SAGE attention (decomposed scores) ----------------
__device__ __forceinline__ unsigned fenc(float f) {
    unsigned u = __float_as_uint(f);
    return (u & 0x80000000u) ? ~u : (u | 0x80000000u);
}
__device__ __forceinline__ float fdec(unsigned u) {
    u = (u & 0x80000000u) ? (u & 0x7fffffffu) : ~u;
    return __uint_as_float(u);
}

// p,q per node + init of MENC/SSUM (folded)
__global__ void k_pq(const float* __restrict__ aw) {
    int n = blockIdx.x * 8 + (threadIdx.x >> 5);
    int lane = threadIdx.x & 31;
    if (n >= NN) return;
    float p = 0.f, q = 0.f;
#pragma unroll
    for (int j = lane; j < 256; j += 32) {
        float v = d_XL[n * GD + j];
        p += v * aw[j];
        q += v * aw[256 + j];
    }
#pragma unroll
    for (int o = 16; o; o >>= 1) {
        p += __shfl_xor_sync(0xffffffffu, p, o);
        q += __shfl_xor_sync(0xffffffffu, q, o);
    }
    if (lane == 0) {
        d_P[n] = p; d_Q[n] = q;
        d_MENC[n] = 0x007fffffu;   // fenc(-inf)
        d_SSUM[n] = 0.f;
    }
}

__global__ void k_edge1(const int* __restrict__ ei, const float* __restrict__ ea,
                        const float* __restrict__ aw, const float* __restrict__ ab) {
    int e = blockIdx.x * 256 + threadIdx.x;
    if (e >= NE) return;
    int row = ei[e], col = ei[NE + e];
    float sc = d_P[row] + d_Q[col] + aw[512] * ea[e] + ab[0];
    d_SC[e] = sc;
    atomicMax(&d_MENC[row], fenc(sc));
}

__global__ void k_edge2(const int* __restrict__ ei) {
    int e = blockIdx.x * 256 + threadIdx.x;
    if (e >= NE) return;
    int row = ei[e];
    float m = fdec(d_MENC[row]);
    float ex = __expf(d_SC[e] - m);
    d_SC[e] = ex;
    atomicAdd(&d_SSUM[row], ex);
}

// CSR aggregation layer 1: alpha division folded in; relu; -> G1
__global__ void __launch_bounds__(256) k_agg(const int* __restrict__ ei,
                                             float* __restrict__ dst) {
    int node = blockIdx.x * 4 + (threadIdx.x >> 6);
    int l = threadIdx.x & 63;
    int beg = d_PTR[node], end = d_PTR[node + 1];
    float4 acc = make_float4(0.f, 0.f, 0.f, 0.f);
    for (int idx = beg; idx < end; idx++) {
        int e = d_EID[idx];
        int row = ei[e];
        float alpha = __fdividef(d_SC[e], d_SSUM[row] + 1e-16f);
        float4 v = *(const float4*)&d_XL[(size_t)row * GD + l * 4];
        acc.x += alpha * v.x; acc.y += alpha * v.y;
        acc.z += alpha * v.z; acc.w += alpha * v.w;
    }
    float4 o;
    o.x = fmaxf(acc.x, 0.f); o.y = fmaxf(acc.y, 0.f);
    o.z = fmaxf(acc.z, 0.f); o.w = fmaxf(acc.w, 0.f);
    *(float4*)&dst[(size_t)node * GD + l * 4] = o;
}

// CSR aggregation layer 2 + residual + heads (fused; G2 never stored)
__global__ void __launch_bounds__(256) k_agg2(const int* __restrict__ ei,
                                              const float* __restrict__ addsrc,
                                              const float* __restrict__ impW,
                                              const float* __restrict__ impb,
                                              const float* __restrict__ uncW,
                                              const float* __restrict__ uncb,
                                              float* __restrict__ out) {
    __shared__ float red[4][2][2];
    int nib = threadIdx.x >> 6;
    int node = blockIdx.x * 4 + nib;   // NN % 4 == 0: always valid
    int l = threadIdx.x & 63;
    int beg = d_PTR[node], end = d_PTR[node + 1];
    float4 acc = make_float4(0.f, 0.f, 0.f, 0.f);
    for (int idx = beg; idx < end; idx++) {
        int e = d_EID[idx];
        int row = ei[e];
        float alpha = __fdividef(d_SC[e], d_SSUM[row] + 1e-16f);
        float4 v = *(const float4*)&d_XL[(size_t)row * GD + l * 4];
        acc.x += alpha * v.x; acc.y += alpha * v.y;
        acc.z += alpha * v.z; acc.w += alpha * v.w;
    }
    float4 a4 = *(const float4*)&addsrc[(size_t)node * GD + l * 4];
    float4 o;
    o.x = fmaxf(acc.x, 0.f) + a4.x; o.y = fmaxf(acc.y, 0.f) + a4.y;
    o.z = fmaxf(acc.z, 0.f) + a4.z; o.w = fmaxf(acc.w, 0.f) + a4.w;
    float4 iw = *(const float4*)&impW[l * 4];
    float4 uw = *(const float4*)&uncW[l * 4];
    float pa = o.x * iw.x + o.y * iw.y + o.z * iw.z + o.w * iw.w;
    float pb = o.x * uw.x + o.y * uw.y + o.z * uw.z + o.w * uw.w;
#pragma unroll
    for (int off = 16; off; off >>= 1) {
        pa += __shfl_xor_sync(0xffffffffu, pa, off);
        pb += __shfl_xor_sync(0xffffffffu, pb, off);
    }
    int half = (threadIdx.x >> 5) & 1;
    if ((threadIdx.x & 31) == 0) {
        red[nib][half][0] = pa;
        red[nib][half][1] = pb;
    }
    __syncthreads();
    if (l == 0) {
        float a = red[nib][0][0] + red[nib][1][0] + impb[0];
        float b = red[nib][0][1] + red[nib][1][1] + uncb[0];
        out[node] = tanhf(a);
        out[NN + node] = 1.f / (1.f + expf(-b));
    }
}

// ---------------- host orchestration ----------------
extern "C" void kernel_launch(void* const* d_in, const int* in_sizes, int n_in,
                              void* d_out, int out_size)
{
    const float* x_s = (const float*)d_in[0];
    const float* x_m = (const float*)d_in[1];
    const float* x_l = (const float*)d_in[2];
    const int*   ei  = (const int*)d_in[3];
    const float* ea  = (const float*)d_in[4];
    // scale order here: 0=long, 1=medium, 2=short
    const float* Wih[3] = {(const float*)d_in[13], (const float*)d_in[9], (const float*)d_in[5]};
    const float* Whh[3] = {(const float*)d_in[14], (const float*)d_in[10], (const float*)d_in[6]};
    const float* bih[3] = {(const float*)d_in[15], (const float*)d_in[11], (const float*)d_in[7]};
    const float* bhh[3] = {(const float*)d_in[16], (const float*)d_in[12], (const float*)d_in[8]};
    const float* fW   = (const float*)d_in[17];
    const float* fb   = (const float*)d_in[18];
    const float* g1W  = (const float*)d_in[19];
    const float* g1aw = (const float*)d_in[20];
    const float* g1ab = (const float*)d_in[21];
    const float* g2W  = (const float*)d_in[22];
    const float* g2aw = (const float*)d_in[23];
    const float* g2ab = (const float*)d_in[24];
    const float* impW = (const float*)d_in[25];
    const float* impb = (const float*)d_in[26];
    const float* uncW = (const float*)d_in[27];
    const float* uncb = (const float*)d_in[28];

    void *pWPK, *pFW, *pG1W, *pG2W, *pBIAS;
    void *pCOMB, *pTEMB, *pXL, *pG1, *pCNT, *pCUR;
    cudaGetSymbolAddress(&pWPK, d_WPK);
    cudaGetSymbolAddress(&pFW, d_FWPK);
    cudaGetSymbolAddress(&pG1W, d_G1PK);
    cudaGetSymbolAddress(&pG2W, d_G2PK);
    cudaGetSymbolAddress(&pBIAS, d_BIAS);
    cudaGetSymbolAddress(&pCOMB, d_COMB);
    cudaGetSymbolAddress(&pTEMB, d_TEMB);
    cudaGetSymbolAddress(&pXL, d_XL);
    cudaGetSymbolAddress(&pG1, d_G1);
    cudaGetSymbolAddress(&pCNT, d_CNT);
    cudaGetSymbolAddress(&pCUR, d_CUR);
    unsigned* WPKp = (unsigned*)pWPK;
    float* BIASp = (float*)pBIAS;
    float* COMB = (float*)pCOMB; float* TEMB = (float*)pTEMB;
    float* XL = (float*)pXL;
    float* G1 = (float*)pG1;

    cudaFuncSetAttribute(gru_persist,
                         cudaFuncAttributeMaxDynamicSharedMemorySize, PERSIST_SMEM);

    // ---- fold biases + repack weights ----
    for (int s = 0; s < 3; s++)
        k_prep_bias<<<1, 768>>>(bih[s], bhh[s], s);
    k_pack<<<(3 * 20 * CHUNK_WORDS + 255) / 256, 256>>>(
        Whh[0], Wih[0], Whh[1], Wih[1], Whh[2], Wih[2]);
    k_packW<<<(4 * 12 * 2048 + 255) / 256, 256>>>(fW, (unsigned*)pFW, 256, 768);
    k_packW<<<(4 * 4 * 2048 + 255) / 256, 256>>>(g1W, (unsigned*)pG1W, 256, 256);
    k_packW<<<(4 * 4 * 2048 + 255) / 256, 256>>>(g2W, (unsigned*)pG2W, 256, 256);

    // ---- CSR build (edge_index reused by both SAGE layers) ----
    cudaMemsetAsync(pCNT, 0, NN * sizeof(int));
    cudaMemsetAsync(pCUR, 0, NN * sizeof(int));
    k_hist<<<(NE + 255) / 256, 256>>>(ei);
    k_scan<<<1, 1024>>>();
    k_scatter<<<(NE + 255) / 256, 256>>>(ei);

    // ---- persistent recurrence (finals written directly into COMB) ----
    gru_persist<<<3 * MB, 1024, PERSIST_SMEM>>>(
        COMB, WPKp, x_l, x_m, x_s, BIASp, bhh[0], bhh[1], bhh[2]);

    // ---- fusion ----
    dim3 gH((NN + 127) / 128, 4);
    gemm_h<<<gH, 256>>>(COMB, 768, (unsigned*)pFW, fb, TEMB, NN, 1);

    // ---- SAGE layer 1 ----
    gemm_h<<<gH, 256>>>(TEMB, 256, (unsigned*)pG1W, nullptr, XL, NN, 0);
    k_pq<<<(NN + 7) / 8, 256>>>(g1aw);
    k_edge1<<<(NE + 255) / 256, 256>>>(ei, ea, g1aw, g1ab);
    k_edge2<<<(NE + 255) / 256, 256>>>(ei);
    k_agg<<<NN / 4, 256>>>(ei, G1);

    // ---- SAGE layer 2 (aggregation + residual + heads fused) ----
    gemm_h<<<gH, 256>>>(G1, 256, (unsigned*)pG2W, nullptr, XL, NN, 0);
    k_pq<<<(NN + 7) / 8, 256>>>(g2aw);
    k_edge1<<<(NE + 255) / 256, 256>>>(ei, ea, g2aw, g2ab);
    k_edge2<<<(NE + 255) / 256, 256>>>(ei);
    k_agg2<<<NN / 4, 256>>>(ei, TEMB, impW, impb, uncW, uncb, (float*)d_out);
}

// round 17
// speedup vs baseline: 1.1024x; 1.0008x over previous
#include <cuda_runtime.h>
#include <cuda_fp16.h>

#define NN 10000
#define NE 320000
#define FD 64
#define HD 256
#define GD 256
#define H3 768
#define MB 79                 // blocks per scale (ceil 10000/128)

#define ASTH 264              // h tile smem stride (halves)
#define XSTH 72               // x tile smem stride (halves)
#define ASM_H (128 * ASTH)    // halves per A tile (33792)
#define XSM_H (128 * XSTH)
#define CHUNK_WORDS 6144      // 192 rows x 64 halves = 24576 B
#define CHUNK_BYTES 24576
// smem: [ring 3x24576][Ah0][Ah1][Xh][mbar]
#define AH0_OFF (3 * CHUNK_BYTES)
#define AH1_OFF (AH0_OFF + ASM_H * 2)
#define XH_OFF (AH1_OFF + ASM_H * 2)
#define MB_OFF (XH_OFF + XSM_H * 2)
#define PERSIST_SMEM (MB_OFF + 32)

// ---------------- static scratch ----------------
__device__ unsigned d_WPK[3 * 20 * CHUNK_WORDS];  // repacked fp16 GRU weights
__device__ unsigned d_FWPK[256 / 64 * 768 / 64 * 2048];  // fusion W packed
__device__ unsigned d_G1PK[256 / 64 * 256 / 64 * 2048];
__device__ unsigned d_G2PK[256 / 64 * 256 / 64 * 2048];
__device__ float d_BIAS[3 * 768];
__device__ float d_COMB[NN * H3];
__device__ float d_TEMB[NN * GD];
__device__ __half d_XLH[NN * GD];
__device__ __half d_G1H[NN * GD];
__device__ float d_P[NN];
__device__ float d_Q[NN];
__device__ float d_SSUM[NN];
__device__ unsigned d_MENC[NN];
__device__ float d_SC[NE];
__device__ int d_CNT[NN];
__device__ int d_PTR[NN + 1];
__device__ int d_CUR[NN];
__device__ int d_EID[NE];

// ---------------- helpers ----------------
__device__ __forceinline__ float fsig(float x) {
    return __fdividef(1.f, 1.f + __expf(-x));
}
__device__ __forceinline__ float ftanh(float x) {
    x = fminf(fmaxf(x, -15.f), 15.f);
    float e = __expf(-2.f * x);
    return __fdividef(1.f - e, 1.f + e);
}

__device__ __forceinline__ unsigned smem_u32(const void* p) {
    return (unsigned)__cvta_generic_to_shared(p);
}

__device__ __forceinline__ void mma_f16(float* c, const unsigned* a, const unsigned* b) {
    asm volatile(
        "mma.sync.aligned.m16n8k16.row.col.f32.f16.f16.f32 "
        "{%0,%1,%2,%3},{%4,%5,%6,%7},{%8,%9},{%0,%1,%2,%3};"
        : "+f"(c[0]), "+f"(c[1]), "+f"(c[2]), "+f"(c[3])
        : "r"(a[0]), "r"(a[1]), "r"(a[2]), "r"(a[3]), "r"(b[0]), "r"(b[1]));
}

__device__ __forceinline__ void ldsm_x4(unsigned* r, unsigned addr) {
    asm volatile("ldmatrix.sync.aligned.m8n8.x4.shared.b16 {%0,%1,%2,%3}, [%4];"
                 : "=r"(r[0]), "=r"(r[1]), "=r"(r[2]), "=r"(r[3]) : "r"(addr));
}

#define MBAR_WAIT(addr, par) do {                                               \
    asm volatile(                                                               \
        "{\n\t.reg .pred P1;\n\t"                                               \
        "WAIT_%=:\n\t"                                                          \
        "mbarrier.try_wait.parity.acquire.cta.shared::cta.b64 P1, [%0], %1, 0x989680;\n\t" \
        "@P1 bra.uni DONE_%=;\n\t"                                              \
        "bra.uni WAIT_%=;\n\t"                                                  \
        "DONE_%=:\n\t}"                                                         \
        :: "r"(addr), "r"(par) : "memory");                                     \
} while (0)

// ---------------- bias fold ----------------
__global__ void k_prep_bias(const float* __restrict__ bih,
                            const float* __restrict__ bhh, int s) {
    int i = threadIdx.x;
    d_BIAS[s * 768 + i] = bih[i] + (i < 512 ? bhh[i] : 0.f);
}

// ---------------- GRU weight repack (fragment-ordered chunks) --------------
__global__ void k_pack(const float* __restrict__ whL, const float* __restrict__ wiL,
                       const float* __restrict__ whM, const float* __restrict__ wiM,
                       const float* __restrict__ whS, const float* __restrict__ wiS) {
    int W = blockIdx.x * 256 + threadIdx.x;
    if (W >= 3 * 20 * CHUNK_WORDS) return;
    int s = W / (20 * CHUNK_WORDS);
    int r = W % (20 * CHUNK_WORDS);
    int c = r / CHUNK_WORDS;
    int q = r % CHUNK_WORDS;
    int w = q & 1, lane = (q >> 1) & 31, ks = (q >> 6) & 3, u = (q >> 8) & 1;
    int gc = (q >> 9) % 3, wn = (q >> 9) / 3;
    int jc = c / 5, pc = c % 5;
    int grow = gc * 256 + jc * 64 + wn * 16 + u * 8 + (lane >> 2);
    int k0 = ks * 16 + 2 * (lane & 3) + w * 8;
    const float* wh = (s == 0) ? whL : ((s == 1) ? whM : whS);
    const float* wi = (s == 0) ? wiL : ((s == 1) ? wiM : wiS);
    const float* src = (pc < 4) ? (wh + (size_t)grow * 256 + pc * 64 + k0)
                                : (wi + (size_t)grow * 64 + k0);
    __half2 h2 = __floats2half2_rn(src[0], src[1]);
    d_WPK[W] = *(unsigned*)&h2;
}

// ---------------- generic GEMM weight repack ----------------
__global__ void k_packW(const float* __restrict__ W, unsigned* __restrict__ dst,
                        int N, int K) {
    int idx = blockIdx.x * 256 + threadIdx.x;
    int KC = K >> 6;
    int total = (N >> 6) * KC * 2048;
    if (idx >= total) return;
    int nb = idx / (KC * 2048);
    int r = idx % (KC * 2048);
    int kc = r / 2048;
    int q = r % 2048;
    int w = q & 1, lane = (q >> 1) & 31, ks = (q >> 6) & 3;
    int nt = (q >> 8) & 3, wn = (q >> 10) & 1;
    int n = nb * 64 + wn * 32 + nt * 8 + (lane >> 2);
    int k = kc * 64 + ks * 16 + 2 * (lane & 3) + w * 8;
    __half2 h2 = __floats2half2_rn(W[(size_t)n * K + k], W[(size_t)n * K + k + 1]);
    dst[idx] = *(unsigned*)&h2;
}

// == persistent GRU: 1024 thr, 4m x 8n; 3-slot ring; early next-step issue ==
__global__ void __launch_bounds__(1024) gru_persist(
    float* __restrict__ comb,
    const unsigned* __restrict__ wpk,
    const float* __restrict__ xL, const float* __restrict__ xM,
    const float* __restrict__ xS,
    const float* __restrict__ biasAll,
    const float* __restrict__ bhhL, const float* __restrict__ bhhM,
    const float* __restrict__ bhhS)
{
    extern __shared__ char smraw[];
    unsigned* Ring = (unsigned*)smraw;
    __half* Ah0 = (__half*)(smraw + AH0_OFF);
    __half* Ah1 = (__half*)(smraw + AH1_OFF);
    __half* Xh = (__half*)(smraw + XH_OFF);
    const unsigned ringaddr = smem_u32(smraw);
    const unsigned mbaddr = smem_u32(smraw + MB_OFF);
    const unsigned xh_base = smem_u32(Xh);

    const int tid = threadIdx.x;
    const int s = blockIdx.x / MB;
    const int m0 = (blockIdx.x % MB) * 128;
    const int T = (s == 0) ? 60 : ((s == 1) ? 30 : 8);
    const int co = (2 - s) * 256;   // column offset in COMB (hs|hm|hl)
    const float* xsrc = (s == 0) ? xL : ((s == 1) ? xM : xS);
    const float* bhh = (s == 0) ? bhhL : ((s == 1) ? bhhM : bhhS);
    const float* bias = biasAll + s * 768;

    const int lane = tid & 31, gid = lane >> 2, tig = lane & 3;
    const int warp = tid >> 5;
    const int wm = warp & 3, wn = warp >> 2;   // 4 m-groups x 8 n-octets
    const int lrow = tid >> 3;
    const int cbase = (tid & 7) * 4;
    const int i4 = lane >> 3, r8 = lane & 7;
    const int bq = ((wn >> 1) * 3) * 2 + (wn & 1);   // B frag base (gc adds gc*2)

    if (tid < 3) {
        asm volatile("mbarrier.init.shared.b64 [%0], %1;"
                     :: "r"(mbaddr + tid * 8), "r"(1u) : "memory");
    }
    // zero both A tiles (h0 = 0; rows >= NN stay zero forever)
    {
        unsigned* za = (unsigned*)Ah0;
        for (int i = tid; i < ASM_H; i += 1024) za[i] = 0;
    }
    __syncthreads();

#define ISSUE_CHUNK(cc) do {                                                    \
        int sl_ = (cc) % 3;                                                     \
        unsigned mb_ = mbaddr + sl_ * 8;                                        \
        asm volatile("mbarrier.arrive.expect_tx.shared.b64 _, [%0], %1;"        \
                     :: "r"(mb_), "r"((unsigned)CHUNK_BYTES) : "memory");       \
        unsigned dst_ = ringaddr + sl_ * CHUNK_BYTES;                           \
        const void* src_ = (const char*)wpk +                                   \
                           ((size_t)(s * 20 + (cc))) * CHUNK_BYTES;             \
        asm volatile(                                                           \
            "cp.async.bulk.shared::cluster.global.mbarrier::complete_tx::bytes " \
            "[%0], [%1], %2, [%3];"                                             \
            :: "r"(dst_), "l"(src_), "r"((unsigned)CHUNK_BYTES), "r"(mb_)       \
            : "memory");                                                        \
    } while (0)

    for (int t = 0; t < T; t++) {
        const __half* Acur = (t & 1) ? Ah1 : Ah0;
        __half* Anxt = (t & 1) ? Ah0 : Ah1;
        const unsigned acur_base = smem_u32(Acur);

        if (t == 0 && tid == 0) { ISSUE_CHUNK(0); ISSUE_CHUNK(1); ISSUE_CHUNK(2); }

        // ---- stage x_t (128x64) into SMEM as fp16 ----
        {
            int grow = m0 + lrow;
            bool ok = grow < NN;
            const float* xr = xsrc + ((size_t)grow * T + t) * 64;
            __half* dx = Xh + lrow * XSTH;
#pragma unroll
            for (int q = 0; q < 2; q++) {
                int col = cbase + q * 32;
                float4 v = ok ? *(const float4*)(xr + col)
                              : make_float4(0.f, 0.f, 0.f, 0.f);
                *(__half2*)(dx + col)     = __floats2half2_rn(v.x, v.y);
                *(__half2*)(dx + col + 2) = __floats2half2_rn(v.z, v.w);
            }
        }
        __syncthreads();   // x staged; prev-step epilogue writes visible

#pragma unroll
        for (int jc = 0; jc < 4; jc++) {
            float acc[2][4][4];   // [m-tile][gate ci][reg]
#pragma unroll
            for (int i = 0; i < 2; i++)
#pragma unroll
                for (int j = 0; j < 4; j++)
#pragma unroll
                    for (int r = 0; r < 4; r++) acc[i][j][r] = 0.f;

#pragma unroll
            for (int pc = 0; pc < 5; pc++) {
                const int c = jc * 5 + pc;
                const int slot = c % 3;
                const int nuse = (slot == 2) ? 6 : 7;
                unsigned par = (unsigned)((t * nuse + c / 3) & 1);
                MBAR_WAIT(mbaddr + slot * 8, par);

                const unsigned* Bs = Ring + slot * CHUNK_WORDS;
                const unsigned abase = (pc < 4) ? acur_base : xh_base;
                const int astr = (pc < 4) ? ASTH : XSTH;
                const int kofs = (pc < 4) ? pc * 64 : 0;
                const unsigned arow0 =
                    abase + ((wm * 32 + (i4 & 1) * 8 + r8) * astr + kofs
                             + (i4 >> 1) * 8) * 2;
                const unsigned arow1 = arow0 + (unsigned)(16 * astr * 2);

#pragma unroll
                for (int ks = 0; ks < 4; ks++) {
                    unsigned af0[4], af1[4];
                    ldsm_x4(af0, arow0 + ks * 32);
                    ldsm_x4(af1, arow1 + ks * 32);
#pragma unroll
                    for (int gc = 0; gc < 3; gc++) {
                        const int ci = (pc == 4 && gc == 2) ? 3 : gc;
                        int fb = (((bq + gc * 2) * 4 + ks) * 32 + lane) * 2;
                        uint2 bf = *(const uint2*)(Bs + fb);
                        mma_f16(acc[0][ci], af0, &bf.x);
                        mma_f16(acc[1][ci], af1, &bf.x);
                    }
                }
                // sync every 2nd chunk; recycle slots; prefetch next step at end
                if (c & 1) {
                    __syncthreads();
                    if (tid == 0) {
                        if (c + 2 < 20) ISSUE_CHUNK(c + 2);
                        if (c + 3 < 20) ISSUE_CHUNK(c + 3);
                        if (c == 19 && t < T - 1) {
                            ISSUE_CHUNK(0); ISSUE_CHUNK(1); ISSUE_CHUNK(2);
                        }
                    }
                }
            }

            // ---- epilogue: GRU update; h read/write in SMEM fp16 ----
            const int j0 = jc * 64;
#pragma unroll
            for (int i = 0; i < 2; i++)
#pragma unroll
                for (int h2 = 0; h2 < 2; h2++) {
                    int row = wm * 32 + i * 16 + gid + h2 * 8;
                    if (m0 + row >= NN) continue;
                    int jg = j0 + wn * 8 + 2 * tig;
                    float2 hp = __half22float2(
                        *(const __half2*)(Acur + row * ASTH + jg));
                    float2 ho;
                    {
                        float r0 = fsig(acc[i][0][h2 * 2 + 0] + bias[jg]);
                        float z0 = fsig(acc[i][1][h2 * 2 + 0] + bias[256 + jg]);
                        float n0 = ftanh(acc[i][3][h2 * 2 + 0] + bias[512 + jg] +
                                         r0 * (acc[i][2][h2 * 2 + 0] + bhh[512 + jg]));
                        ho.x = (1.f - z0) * n0 + z0 * hp.x;
                    }
                    {
                        float r1 = fsig(acc[i][0][h2 * 2 + 1] + bias[jg + 1]);
                        float z1 = fsig(acc[i][1][h2 * 2 + 1] + bias[256 + jg + 1]);
                        float n1 = ftanh(acc[i][3][h2 * 2 + 1] + bias[512 + jg + 1] +
                                         r1 * (acc[i][2][h2 * 2 + 1] + bhh[512 + jg + 1]));
                        ho.y = (1.f - z1) * n1 + z1 * hp.y;
                    }
                    *(__half2*)(Anxt + row * ASTH + jg) =
                        __floats2half2_rn(ho.x, ho.y);
                    if (t == T - 1)
                        *(float2*)(comb + (size_t)(m0 + row) * H3 + co + jg) = ho;
                }
        }
    }
#undef ISSUE_CHUNK
}

// ===== fp16 MMA GEMM (double-buffered A, fp32/fp16 in/out, fused P/Q) ======
__global__ void __launch_bounds__(256) gemm_h(
    const void* __restrict__ A, int ahalf, int K,
    const unsigned* __restrict__ Bpk,
    const float* __restrict__ bias,
    void* __restrict__ C, int chalf, int M, int relu,
    const float* __restrict__ pqw)
{
    __shared__ __half Ash[2][128 * 72];
    const int tid = threadIdx.x, lane = tid & 31, warp = tid >> 5;
    const int wm = warp & 3, wn = warp >> 2;
    const int gid = lane >> 2, tig = lane & 3;
    const int i4 = lane >> 3, r8 = lane & 7;
    const int m0 = blockIdx.x * 128;
    const int KC = K >> 6;
    const unsigned* Bbase = Bpk + (size_t)blockIdx.y * KC * 2048;

    float acc[2][4][4];
#pragma unroll
    for (int i = 0; i < 2; i++)
#pragma unroll
        for (int nt = 0; nt < 4; nt++)
#pragma unroll
            for (int r = 0; r < 4; r++) acc[i][nt][r] = 0.f;

    const int srow = tid >> 1, scs = (tid & 1) * 32;
    const bool okrow = (m0 + srow) < M;

#define STAGE_A(kc, buf)                                                        \
    {                                                                           \
        __half* da = Ash[buf] + srow * 72 + scs;                                \
        if (ahalf) {                                                            \
            const uint4* src4 = (const uint4*)((const __half*)A +               \
                (size_t)(m0 + srow) * K + (kc) * 64 + scs);                     \
            uint4 z = make_uint4(0, 0, 0, 0);                                   \
            _Pragma("unroll")                                                   \
            for (int qq = 0; qq < 4; qq++)                                      \
                ((uint4*)da)[qq] = okrow ? src4[qq] : z;                        \
        } else {                                                                \
            const float* ar = (const float*)A +                                 \
                (size_t)(m0 + srow) * K + (kc) * 64 + scs;                      \
            _Pragma("unroll")                                                   \
            for (int qq = 0; qq < 8; qq++) {                                    \
                float4 v = okrow ? *(const float4*)(ar + qq * 4)                \
                                 : make_float4(0.f, 0.f, 0.f, 0.f);             \
                *(__half2*)(da + qq * 4)     = __floats2half2_rn(v.x, v.y);     \
                *(__half2*)(da + qq * 4 + 2) = __floats2half2_rn(v.z, v.w);     \
            }                                                                   \
        }                                                                       \
    }

    STAGE_A(0, 0);
    __syncthreads();

    for (int kc = 0; kc < KC; kc++) {
        if (kc + 1 < KC) STAGE_A(kc + 1, (kc + 1) & 1);
        const unsigned ab = smem_u32(Ash[kc & 1]);
        const unsigned* Bc = Bbase + kc * 2048;
#pragma unroll
        for (int ks = 0; ks < 4; ks++) {
            unsigned af[2][4];
#pragma unroll
            for (int i = 0; i < 2; i++) {
                int arow = wm * 32 + i * 16 + (i4 & 1) * 8 + r8;
                int acol = ks * 16 + (i4 >> 1) * 8;
                ldsm_x4(af[i], ab + (arow * 72 + acol) * 2);
            }
#pragma unroll
            for (int nt = 0; nt < 4; nt++) {
                int fb = (((wn * 4 + nt) * 4 + ks) * 32 + lane) * 2;
                uint2 bf = *(const uint2*)(Bc + fb);
#pragma unroll
                for (int i = 0; i < 2; i++)
                    mma_f16(acc[i][nt], af[i], &bf.x);
            }
        }
        __syncthreads();
    }
#undef STAGE_A

#pragma unroll
    for (int i = 0; i < 2; i++)
#pragma unroll
        for (int h2 = 0; h2 < 2; h2++) {
            int row = m0 + wm * 32 + i * 16 + h2 * 8 + gid;
            if (row >= M) continue;
            float pp = 0.f, qq = 0.f;
#pragma unroll
            for (int nt = 0; nt < 4; nt++) {
                int col = blockIdx.y * 64 + wn * 32 + nt * 8 + 2 * tig;
                float ox = acc[i][nt][h2 * 2 + 0] + (bias ? bias[col] : 0.f);
                float oy = acc[i][nt][h2 * 2 + 1] + (bias ? bias[col + 1] : 0.f);
                if (relu) { ox = fmaxf(ox, 0.f); oy = fmaxf(oy, 0.f); }
                if (chalf)
                    *(__half2*)((__half*)C + (size_t)row * GD + col) =
                        __floats2half2_rn(ox, oy);
                else
                    *(float2*)((float*)C + (size_t)row * GD + col) =
                        make_float2(ox, oy);
                if (pqw) {
                    pp += ox * pqw[col] + oy * pqw[col + 1];
                    qq += ox * pqw[256 + col] + oy * pqw[256 + col + 1];
                }
            }
            if (pqw) {
                atomicAdd(&d_P[row], pp);
                atomicAdd(&d_Q[row], qq);
            }
        }
}

// ---------------- CSR build (by destination col) ----------------
__global__ void k_hist(const int* __restrict__ ei) {
    int e = blockIdx.x * 256 + threadIdx.x;
    if (e < NE) atomicAdd(&d_CNT[ei[NE + e]], 1);
}

__global__ void k_scan() {   // 1 block, 1024 threads
    __shared__ int part[1024];
    int t = threadIdx.x;
    int base = t * 10;
    int sum = 0;
#pragma unroll
    for (int i = 0; i < 10; i++) {
        int idx = base + i;
        if (idx < NN) sum += d_CNT[idx];
    }
    part[t] = sum;
    __syncthreads();
    for (int off = 1; off < 1024; off <<= 1) {
        int v = (t >= off) ? part[t - off] : 0;
        __syncthreads();
        part[t] += v;
        __syncthreads();
    }
    int run = (t > 0) ? part[t - 1] : 0;
#pragma unroll
    for (int i = 0; i < 10; i++) {
        int idx = base + i;
        if (idx < NN) {
            d_PTR[idx] = run;
            run += d_CNT[idx];
        }
    }
    if (t == 0) d_PTR[NN] = part[1023];
}

__global__ void k_scatter(const int* __restrict__ ei) {
    int e = blockIdx.x * 256 + threadIdx.x;
    if (e >= NE) return;
    int col = ei[NE + e];
    int pos = atomicAdd(&d_CUR[col], 1);
    d_EID[d_PTR[col] + pos] = e;
}

// ---------------- SAGE attention ----------------
__device__ __forceinline__ unsigned fenc(float f) {
    unsigned u = __float_as_uint(f);
    return (u & 0x80000000u) ? ~u : (u | 0x80000000u);
}
__device__ __forceinline__ float fdec(unsigned u) {
    u = (u & 0x80000000u) ? (u & 0x7fffffffu) : ~u;
    return __uint_as_float(u);
}

// per-layer init: MENC/SSUM + P/Q accumulators
__global__ void k_init() {
    int n = blockIdx.x * 256 + threadIdx.x;
    if (n < NN) {
        d_MENC[n] = 0x007fffffu;   // fenc(-inf)
        d_SSUM[n] = 0.f;
        d_P[n] = 0.f;
        d_Q[n] = 0.f;
    }
}

__global__ void k_edge1(const int* __restrict__ ei, const float* __restrict__ ea,
                        const float* __restrict__ aw, const float* __restrict__ ab) {
    int e = blockIdx.x * 256 + threadIdx.x;
    if (e >= NE) return;
    int row = ei[e], col = ei[NE + e];
    float sc = d_P[row] + d_Q[col] + aw[512] * ea[e] + ab[0];
    d_SC[e] = sc;
    atomicMax(&d_MENC[row], fenc(sc));
}

__global__ void k_edge2(const int* __restrict__ ei) {
    int e = blockIdx.x * 256 + threadIdx.x;
    if (e >= NE) return;
    int row = ei[e];
    float m = fdec(d_MENC[row]);
    float ex = __expf(d_SC[e] - m);
    d_SC[e] = ex;
    atomicAdd(&d_SSUM[row], ex);
}

// CSR aggregation layer 1: alpha div folded; relu; -> G1 (fp16)
__global__ void __launch_bounds__(256) k_agg(const int* __restrict__ ei,
                                             __half* __restrict__ dst) {
    int node = blockIdx.x * 4 + (threadIdx.x >> 6);
    int l = threadIdx.x & 63;
    int beg = d_PTR[node], end = d_PTR[node + 1];
    float4 acc = make_float4(0.f, 0.f, 0.f, 0.f);
    for (int idx = beg; idx < end; idx++) {
        int e = d_EID[idx];
        int row = ei[e];
        float alpha = __fdividef(d_SC[e], d_SSUM[row] + 1e-16f);
        uint2 u = *(const uint2*)&d_XLH[(size_t)row * GD + l * 4];
        float2 f01 = __half22float2(*(__half2*)&u.x);
        float2 f23 = __half22float2(*(__half2*)&u.y);
        acc.x += alpha * f01.x; acc.y += alpha * f01.y;
        acc.z += alpha * f23.x; acc.w += alpha * f23.y;
    }
    __half2 h01 = __floats2half2_rn(fmaxf(acc.x, 0.f), fmaxf(acc.y, 0.f));
    __half2 h23 = __floats2half2_rn(fmaxf(acc.z, 0.f), fmaxf(acc.w, 0.f));
    uint2 st;
    st.x = *(unsigned*)&h01; st.y = *(unsigned*)&h23;
    *(uint2*)&dst[(size_t)node * GD + l * 4] = st;
}

// CSR aggregation layer 2 + residual + heads (fused)
__global__ void __launch_bounds__(256) k_agg2(const int* __restrict__ ei,
                                              const float* __restrict__ addsrc,
                                              const float* __restrict__ impW,
                                              const float* __restrict__ impb,
                                              const float* __restrict__ uncW,
                                              const float* __restrict__ uncb,
                                              float* __restrict__ out) {
    __shared__ float red[4][2][2];
    int nib = threadIdx.x >> 6;
    int node = blockIdx.x * 4 + nib;   // NN % 4 == 0
    int l = threadIdx.x & 63;
    int beg = d_PTR[node], end = d_PTR[node + 1];
    float4 acc = make_float4(0.f, 0.f, 0.f, 0.f);
    for (int idx = beg; idx < end; idx++) {
        int e = d_EID[idx];
        int row = ei[e];
        float alpha = __fdividef(d_SC[e], d_SSUM[row] + 1e-16f);
        uint2 u = *(const uint2*)&d_XLH[(size_t)row * GD + l * 4];
        float2 f01 = __half22float2(*(__half2*)&u.x);
        float2 f23 = __half22float2(*(__half2*)&u.y);
        acc.x += alpha * f01.x; acc.y += alpha * f01.y;
        acc.z += alpha * f23.x; acc.w += alpha * f23.y;
    }
    float4 a4 = *(const float4*)&addsrc[(size_t)node * GD + l * 4];
    float4 o;
    o.x = fmaxf(acc.x, 0.f) + a4.x; o.y = fmaxf(acc.y, 0.f) + a4.y;
    o.z = fmaxf(acc.z, 0.f) + a4.z; o.w = fmaxf(acc.w, 0.f) + a4.w;
    float4 iw = *(const float4*)&impW[l * 4];
    float4 uw = *(const float4*)&uncW[l * 4];
    float pa = o.x * iw.x + o.y * iw.y + o.z * iw.z + o.w * iw.w;
    float pb = o.x * uw.x + o.y * uw.y + o.z * uw.z + o.w * uw.w;
#pragma unroll
    for (int off = 16; off; off >>= 1) {
        pa += __shfl_xor_sync(0xffffffffu, pa, off);
        pb += __shfl_xor_sync(0xffffffffu, pb, off);
    }
    int half = (threadIdx.x >> 5) & 1;
    if ((threadIdx.x & 31) == 0) {
        red[nib][half][0] = pa;
        red[nib][half][1] = pb;
    }
    __syncthreads();
    if (l == 0) {
        float a = red[nib][0][0] + red[nib][1][0] + impb[0];
        float b = red[nib][0][1] + red[nib][1][1] + uncb[0];
        out[node] = tanhf(a);
        out[NN + node] = 1.f / (1.f + expf(-b));
    }
}

// ---------------- host orchestration ----------------
extern "C" void kernel_launch(void* const* d_in, const int* in_sizes, int n_in,
                              void* d_out, int out_size)
{
    const float* x_s = (const float*)d_in[0];
    const float* x_m = (const float*)d_in[1];
    const float* x_l = (const float*)d_in[2];
    const int*   ei  = (const int*)d_in[3];
    const float* ea  = (const float*)d_in[4];
    // scale order here: 0=long, 1=medium, 2=short
    const float* Wih[3] = {(const float*)d_in[13], (const float*)d_in[9], (const float*)d_in[5]};
    const float* Whh[3] = {(const float*)d_in[14], (const float*)d_in[10], (const float*)d_in[6]};
    const float* bih[3] = {(const float*)d_in[15], (const float*)d_in[11], (const float*)d_in[7]};
    const float* bhh[3] = {(const float*)d_in[16], (const float*)d_in[12], (const float*)d_in[8]};
    const float* fW   = (const float*)d_in[17];
    const float* fb   = (const float*)d_in[18];
    const float* g1W  = (const float*)d_in[19];
    const float* g1aw = (const float*)d_in[20];
    const float* g1ab = (const float*)d_in[21];
    const float* g2W  = (const float*)d_in[22];
    const float* g2aw = (const float*)d_in[23];
    const float* g2ab = (const float*)d_in[24];
    const float* impW = (const float*)d_in[25];
    const float* impb = (const float*)d_in[26];
    const float* uncW = (const float*)d_in[27];
    const float* uncb = (const float*)d_in[28];

    void *pWPK, *pFW, *pG1W, *pG2W, *pBIAS;
    void *pCOMB, *pTEMB, *pXLH, *pG1H, *pCNT, *pCUR;
    cudaGetSymbolAddress(&pWPK, d_WPK);
    cudaGetSymbolAddress(&pFW, d_FWPK);
    cudaGetSymbolAddress(&pG1W, d_G1PK);
    cudaGetSymbolAddress(&pG2W, d_G2PK);
    cudaGetSymbolAddress(&pBIAS, d_BIAS);
    cudaGetSymbolAddress(&pCOMB, d_COMB);
    cudaGetSymbolAddress(&pTEMB, d_TEMB);
    cudaGetSymbolAddress(&pXLH, d_XLH);
    cudaGetSymbolAddress(&pG1H, d_G1H);
    cudaGetSymbolAddress(&pCNT, d_CNT);
    cudaGetSymbolAddress(&pCUR, d_CUR);
    unsigned* WPKp = (unsigned*)pWPK;
    float* BIASp = (float*)pBIAS;
    float* COMB = (float*)pCOMB; float* TEMB = (float*)pTEMB;
    __half* XLH = (__half*)pXLH;
    __half* G1H = (__half*)pG1H;

    cudaFuncSetAttribute(gru_persist,
                         cudaFuncAttributeMaxDynamicSharedMemorySize, PERSIST_SMEM);

    // ---- fold biases + repack weights ----
    for (int s = 0; s < 3; s++)
        k_prep_bias<<<1, 768>>>(bih[s], bhh[s], s);
    k_pack<<<(3 * 20 * CHUNK_WORDS + 255) / 256, 256>>>(
        Whh[0], Wih[0], Whh[1], Wih[1], Whh[2], Wih[2]);
    k_packW<<<(4 * 12 * 2048 + 255) / 256, 256>>>(fW, (unsigned*)pFW, 256, 768);
    k_packW<<<(4 * 4 * 2048 + 255) / 256, 256>>>(g1W, (unsigned*)pG1W, 256, 256);
    k_packW<<<(4 * 4 * 2048 + 255) / 256, 256>>>(g2W, (unsigned*)pG2W, 256, 256);

    // ---- CSR build + layer-1 softmax/PQ init ----
    cudaMemsetAsync(pCNT, 0, NN * sizeof(int));
    cudaMemsetAsync(pCUR, 0, NN * sizeof(int));
    k_hist<<<(NE + 255) / 256, 256>>>(ei);
    k_scan<<<1, 1024>>>();
    k_scatter<<<(NE + 255) / 256, 256>>>(ei);
    k_init<<<(NN + 255) / 256, 256>>>();

    // ---- persistent recurrence (finals written directly into COMB) ----
    gru_persist<<<3 * MB, 1024, PERSIST_SMEM>>>(
        COMB, WPKp, x_l, x_m, x_s, BIASp, bhh[0], bhh[1], bhh[2]);

    // ---- fusion ----
    dim3 gH((NN + 127) / 128, 4);
    gemm_h<<<gH, 256>>>(COMB, 0, 768, (unsigned*)pFW, fb, TEMB, 0, NN, 1, nullptr);

    // ---- SAGE layer 1 (XL fp16; P/Q fused into gemm epilogue) ----
    gemm_h<<<gH, 256>>>(TEMB, 0, 256, (unsigned*)pG1W, nullptr, XLH, 1, NN, 0, g1aw);
    k_edge1<<<(NE + 255) / 256, 256>>>(ei, ea, g1aw, g1ab);
    k_edge2<<<(NE + 255) / 256, 256>>>(ei);
    k_agg<<<NN / 4, 256>>>(ei, G1H);
    k_init<<<(NN + 255) / 256, 256>>>();   // reset for layer 2

    // ---- SAGE layer 2 (aggregation + residual + heads fused) ----
    gemm_h<<<gH, 256>>>(G1H, 1, 256, (unsigned*)pG2W, nullptr, XLH, 1, NN, 0, g2aw);
    k_edge1<<<(NE + 255) / 256, 256>>>(ei, ea, g2aw, g2ab);
    k_edge2<<<(NE + 255) / 256, 256>>>(ei);
    k_agg2<<<NN / 4, 256>>>(ei, TEMB, impW, impb, uncW, uncb, (float*)d_out);
}